// round 16
// baseline (speedup 1.0000x reference)
#include <cuda_runtime.h>
#include <stdint.h>
#include <math_constants.h>

// WinnerTakeAll: per-row top-k (k=1000), rows of 20000 fp32, 4096 rows.
// NT=512, 4 CTAs/SM (dynamic SMEM ~55.5KB). Single-threshold slot-direct:
//  1. t_lo = mu+1.514*sigma (expect ~1300 >= t_lo) from 2048 samples.
//  2. hot stream (FSETP+FSEL only): out = v>=t_lo ? v : 0; ALL candidates'
//     keys+indices -> per-thread SMEM slots (mean 2.6/thread, SLOTS=15).
//  3. tail (SMEM only): normalized 1-pass hist over [t_lo, mu+2.3*sigma]
//     (clamped top bin), select2 -> bin with <=32 keys -> warp-register exact
//     k-th select -> zero losers (u < u_t).
//  4. guards (slot overflow, ccount<k, bin>32, tie straddle) -> exact slow
//     path (full radix, rewrites entire row).

#define DCOLS    20000
#define KKEEP    1000u
#define NT       512
#define NWARP    16
#define NBINS    2048
#define SLOTS    15
#define CAND_CAP 1024
#define ZLO      1.514f
#define ZCAP     2.30f

struct Smem {
    union {
        struct {                       // fast path: per-thread slots
            uint32_t skey[NT * SLOTS]; // 30720 B
            uint16_t sidx[NT * SLOTS]; // 15360 B
        } f;
        struct {                       // slow path: compact candidate arrays
            uint32_t cand[CAND_CAP];   // 4096 B
            uint16_t cidx[CAND_CAP];   // 2048 B
        } sp;
    } u;                               // 46080 B
    uint32_t hist[NBINS];              // 8192 B
    uint32_t segsum[256];              // 1 KB (select2 scratch + tie-collect)
    float    redsum[NWARP], redsq[NWARP];
    float    t_lo, t_cap;
    uint32_t cand_count, overflow, tcnt;
    uint32_t bA, kkA, bB, kkB, bC, kkC, cntC;
};

__device__ __forceinline__ uint32_t f2u(float f) {
    uint32_t b = __float_as_uint(f);
    return b ^ ((b & 0x80000000u) ? 0xFFFFFFFFu : 0x80000000u);
}
__device__ __forceinline__ float u2f(uint32_t u) {
    uint32_t b = (u & 0x80000000u) ? (u ^ 0x80000000u) : (u ^ 0xFFFFFFFFu);
    return __uint_as_float(b);
}

// Warp-aggregated histogram add (ALL 32 lanes participate). Slow path only.
__device__ __forceinline__ void hist_add(uint32_t* hist, uint32_t bin, bool valid) {
    uint32_t key = valid ? bin : 0xFFFFFFFFu;
    unsigned m = __match_any_sync(0xFFFFFFFFu, key);
    int leader = __ffs(m) - 1;
    if (valid && (int)(threadIdx.x & 31) == leader)
        atomicAdd(&hist[bin], (uint32_t)__popc(m));
}

// Serial top-down scan (slow path only; warp 0).
__device__ __forceinline__ void select_from_top(const uint32_t* hist, int nbins, uint32_t kk,
                                                uint32_t* out_bin, uint32_t* out_kk, uint32_t* out_cnt) {
    int lane = threadIdx.x & 31;
    uint32_t cum = 0;
    for (int base = nbins - 32; base >= 0; base -= 32) {
        uint32_t v = hist[base + 31 - lane];
        uint32_t incl = v;
        #pragma unroll
        for (int off = 1; off < 32; off <<= 1) {
            uint32_t t = __shfl_up_sync(0xFFFFFFFFu, incl, off);
            if (lane >= off) incl += t;
        }
        uint32_t total = __shfl_sync(0xFFFFFFFFu, incl, 31);
        unsigned hm = __ballot_sync(0xFFFFFFFFu, cum + incl >= kk);
        if (hm) {
            int l = __ffs(hm) - 1;
            if (lane == l) {
                *out_bin = (uint32_t)(base + 31 - l);
                *out_kk  = kk - cum - (incl - v);
                *out_cnt = v;
            }
            return;
        }
        cum += total;
    }
    if (lane == 0) { *out_bin = 0; *out_kk = 1; *out_cnt = 1; }
}

// Block-parallel select: segment sums (8 bins/seg), then warp 0 scans segments.
__device__ __forceinline__ void select2(Smem* s, const uint32_t* hist, int nbins, uint32_t kk,
                                        uint32_t* out_bin, uint32_t* out_kk, uint32_t* out_cnt,
                                        int tid) {
    int nseg = nbins >> 3;
    const uint4* h4 = reinterpret_cast<const uint4*>(hist);
    for (int i = tid; i < nseg; i += NT) {
        uint4 x = h4[2 * i], y = h4[2 * i + 1];
        s->segsum[i] = x.x + x.y + x.z + x.w + y.x + y.y + y.z + y.w;
    }
    __syncthreads();
    if (tid < 32) {
        int lane = tid;
        uint32_t cum = 0;
        bool done = false;
        for (int base = nseg - 32; base >= 0 && !done; base -= 32) {
            uint32_t v = s->segsum[base + 31 - lane];
            uint32_t incl = v;
            #pragma unroll
            for (int off = 1; off < 32; off <<= 1) {
                uint32_t t = __shfl_up_sync(0xFFFFFFFFu, incl, off);
                if (lane >= off) incl += t;
            }
            uint32_t total = __shfl_sync(0xFFFFFFFFu, incl, 31);
            unsigned hm = __ballot_sync(0xFFFFFFFFu, cum + incl >= kk);
            if (hm) {
                int l = __ffs(hm) - 1;
                if (lane == l) {
                    int seg = base + 31 - l;
                    uint32_t kk_s = kk - cum - (incl - v);
                    for (int b = seg * 8 + 7; b >= seg * 8; b--) {
                        uint32_t c = hist[b];
                        if (kk_s <= c) { *out_bin = (uint32_t)b; *out_kk = kk_s; *out_cnt = c; break; }
                        kk_s -= c;
                    }
                }
                done = true;
            }
            cum += total;
        }
        if (!done && lane == 0) { *out_bin = 0; *out_kk = 1; *out_cnt = 1; }
    }
    __syncthreads();
}

extern "C" __global__ void __launch_bounds__(NT, 4)
wta_kernel(const float* __restrict__ in, float* __restrict__ out, int rows) {
    extern __shared__ uint8_t smem_raw[];
    Smem& s = *reinterpret_cast<Smem*>(smem_raw);

    const int row = blockIdx.x;
    if (row >= rows) return;
    const int tid = threadIdx.x;
    const int lane = tid & 31;
    const int w = tid >> 5;

    const float*  rowf = in + (size_t)row * DCOLS;
    const float4* rowp = reinterpret_cast<const float4*>(rowf);
    float4* outp = reinterpret_cast<float4*>(out + (size_t)row * DCOLS);
    float*  outf = out + (size_t)row * DCOLS;
    const int nvec = DCOLS / 4;                 // 5000
    const int niter = (nvec + NT - 1) / NT;     // 10

    if (tid == 0) { s.cand_count = 0; s.overflow = 0; s.tcnt = 0; }
    reinterpret_cast<uint4*>(s.hist)[tid] = make_uint4(0, 0, 0, 0);   // 8KB clear

    // ---- phase 1: threshold from sample mean/std (2048 samples) ----
    {
        float4 a = rowp[tid];
        float sum = a.x + a.y + a.z + a.w;
        float sq = fmaf(a.x, a.x, fmaf(a.y, a.y, fmaf(a.z, a.z, a.w * a.w)));
        #pragma unroll
        for (int off = 16; off > 0; off >>= 1) {
            sum += __shfl_down_sync(0xFFFFFFFFu, sum, off);
            sq  += __shfl_down_sync(0xFFFFFFFFu, sq,  off);
        }
        if (lane == 0) { s.redsum[w] = sum; s.redsq[w] = sq; }
        __syncthreads();
        if (tid == 0) {
            float ts = 0.f, tq = 0.f;
            #pragma unroll
            for (int i = 0; i < NWARP; i++) { ts += s.redsum[i]; tq += s.redsq[i]; }
            float mu = ts * (1.0f / 2048.0f);
            float var = tq * (1.0f / 2048.0f) - mu * mu;
            float sd = sqrtf(fmaxf(var, 0.0f));
            s.t_lo  = fmaf(ZLO,  sd, mu);
            s.t_cap = fmaf(ZCAP, sd, mu);
        }
        __syncthreads();
    }
    const float t_lo = s.t_lo;

    // ---- phase 2: hot stream (FSETP + FSEL + rare slot store) ----
    uint32_t nloc = 0;
    const uint32_t slotbase = (uint32_t)tid * SLOTS;
    const float NEG = __int_as_float(0xFF800000);
    #pragma unroll
    for (int it = 0; it < 10; it++) {
        int i = tid + it * NT;
        bool valid = i < nvec;
        float4 v = make_float4(NEG, NEG, NEG, NEG);
        if (valid) v = rowp[i];
        float vv[4] = { v.x, v.y, v.z, v.w };
        float ov[4];
        #pragma unroll
        for (int j = 0; j < 4; j++) {
            bool ge = vv[j] >= t_lo;           // candidate (winner or loser)
            ov[j] = ge ? vv[j] : 0.0f;
            if (ge) {
                if (nloc < SLOTS) {
                    s.u.f.skey[slotbase + nloc] = f2u(vv[j]);
                    s.u.f.sidx[slotbase + nloc] = (uint16_t)(i * 4 + j);
                }
                nloc++;
            }
        }
        if (valid) {
            float4 o; o.x = ov[0]; o.y = ov[1]; o.z = ov[2]; o.w = ov[3];
            outp[i] = o;
        }
    }
    uint32_t nstore = nloc < SLOTS ? nloc : SLOTS;
    if (nloc > SLOTS) s.overflow = 1;

    // ---- reduce ccount (one warp-reduce, one atomic/warp) ----
    uint32_t my_band = nstore;
    #pragma unroll
    for (int off = 16; off > 0; off >>= 1)
        my_band += __shfl_down_sync(0xFFFFFFFFu, my_band, off);
    if (lane == 0 && my_band) atomicAdd(&s.cand_count, my_band);
    __syncthreads();

    const uint32_t ccount = s.cand_count;
    bool need_slow = !((!s.overflow) && (ccount >= KKEEP));

    if (!need_slow) {
        // ===== FAST TAIL: slot-direct, SMEM only, kk = KKEEP =====
        const uint32_t u_lo = f2u(t_lo);
        uint32_t R = f2u(s.t_cap) - u_lo;
        if (R == 0) R = 1;
        const int shift = __clz(R);

        // 1-pass normalized histogram (clamped top bin preserves order)
        for (uint32_t n = 0; n < nstore; n++) {
            uint32_t d = s.u.f.skey[slotbase + n] - u_lo;
            if (d > R) d = R;
            atomicAdd(&s.hist[(d << shift) >> 21], 1u);
        }
        __syncthreads();
        select2(&s, s.hist, NBINS, KKEEP, &s.bA, &s.kkA, &s.cntC, tid);
        const uint32_t nbin = s.bA;
        const uint32_t kk1 = s.kkA;
        const uint32_t cnt1 = s.cntC;

        if (cnt1 > 32) {
            need_slow = true;                   // pathological mass in one bin
        } else {
            // collect the <=32 keys of the target bin
            for (uint32_t n = 0; n < nstore; n++) {
                uint32_t u = s.u.f.skey[slotbase + n];
                uint32_t d = u - u_lo;
                if (d > R) d = R;
                if (((d << shift) >> 21) == nbin) {
                    uint32_t pos = atomicAdd(&s.tcnt, 1u);
                    s.segsum[pos] = u;          // pos < 32 (cnt1 <= 32)
                }
            }
            __syncthreads();
            // warp-register exact selection among <=32 keys
            if (tid < 32) {
                uint32_t myu = (tid < (int)cnt1) ? s.segsum[tid] : 0;
                uint32_t gt = 0, eq = 0;
                for (uint32_t p = 0; p < cnt1; p++) {
                    uint32_t up = __shfl_sync(0xFFFFFFFFu, myu, p);
                    gt += (up > myu);
                    eq += (up == myu);
                }
                bool sel = (tid < (int)cnt1) && (gt < kk1) && (kk1 <= gt + eq);
                unsigned m = __ballot_sync(0xFFFFFFFFu, sel);
                int l = __ffs(m) - 1;
                if (tid == l) { s.bB = myu; s.kkB = kk1 - gt; s.bC = eq; }
            }
            __syncthreads();
            const uint32_t u_t = s.bB;
            const uint32_t A = s.kkB;
            const uint32_t T = s.bC;
            if (A != T) {
                need_slow = true;               // ties straddle boundary (rare)
            } else {
                // zero losers straight from slots
                for (uint32_t n = 0; n < nstore; n++) {
                    uint32_t u = s.u.f.skey[slotbase + n];
                    if (u < u_t) outf[s.u.f.sidx[slotbase + n]] = 0.0f;
                }
                return;
            }
        }
    }

    // ================= SLOW PATH (rare; rewrites entire row) =================
    __syncthreads();
    reinterpret_cast<uint4*>(s.hist)[tid] = make_uint4(0, 0, 0, 0);
    if (tid == 0) s.cand_count = 0;
    __syncthreads();

    #pragma unroll 1
    for (int it = 0; it < niter; it++) {
        int i = tid + it * NT;
        bool valid = i < nvec;
        uint32_t u0 = 0, u1 = 0, u2 = 0, u3 = 0;
        if (valid) {
            float4 v = rowp[i];
            u0 = f2u(v.x); u1 = f2u(v.y); u2 = f2u(v.z); u3 = f2u(v.w);
        }
        hist_add(s.hist, u0 >> 21, valid);
        hist_add(s.hist, u1 >> 21, valid);
        hist_add(s.hist, u2 >> 21, valid);
        hist_add(s.hist, u3 >> 21, valid);
    }
    __syncthreads();
    if (tid < 32) select_from_top(s.hist, NBINS, KKEEP, &s.bA, &s.kkA, &s.cntC);
    __syncthreads();
    const uint32_t b1 = s.bA;
    const uint32_t kk1s = s.kkA;

    #pragma unroll 1
    for (int it = 0; it < niter; it++) {
        int i = tid + it * NT;
        if (i >= nvec) break;
        float4 v = rowp[i];
        float vv[4] = { v.x, v.y, v.z, v.w };
        uint32_t uu[4] = { f2u(v.x), f2u(v.y), f2u(v.z), f2u(v.w) };
        float ov[4];
        #pragma unroll
        for (int j = 0; j < 4; j++) {
            uint32_t bin = uu[j] >> 21;
            ov[j] = (bin > b1) ? vv[j] : 0.0f;
            if (bin == b1) {
                uint32_t pos = atomicAdd(&s.cand_count, 1u);
                if (pos < CAND_CAP) { s.u.sp.cand[pos] = uu[j]; s.u.sp.cidx[pos] = (uint16_t)(i * 4 + j); }
            }
        }
        float4 o; o.x = ov[0]; o.y = ov[1]; o.z = ov[2]; o.w = ov[3];
        outp[i] = o;
    }
    __syncthreads();

    const uint32_t cc2 = s.cand_count;
    const bool use_cand = (cc2 <= CAND_CAP);
    const int nitems = use_cand ? (int)cc2 : DCOLS;
    const int niterB = (nitems + NT - 1) / NT;

    reinterpret_cast<uint4*>(s.hist)[tid] = make_uint4(0, 0, 0, 0);
    __syncthreads();
    #pragma unroll 1
    for (int it = 0; it < niterB; it++) {
        int i = tid + it * NT;
        bool valid = i < nitems;
        uint32_t u = 0;
        if (valid) u = use_cand ? s.u.sp.cand[i] : f2u(rowf[i]);
        valid = valid && (use_cand || ((u >> 21) == b1));
        hist_add(s.hist, (u >> 10) & 0x7FFu, valid);
    }
    __syncthreads();
    if (tid < 32) select_from_top(s.hist, NBINS, kk1s, &s.bB, &s.kkB, &s.cntC);
    __syncthreads();
    const uint32_t b2 = s.bB;
    const uint32_t kk2 = s.kkB;
    const uint32_t pref22 = (b1 << 11) | b2;

    for (int i = tid; i < 1024; i += NT) s.hist[i] = 0;
    __syncthreads();
    #pragma unroll 1
    for (int it = 0; it < niterB; it++) {
        int i = tid + it * NT;
        bool valid = i < nitems;
        uint32_t u = 0;
        if (valid) u = use_cand ? s.u.sp.cand[i] : f2u(rowf[i]);
        valid = valid && ((u >> 10) == pref22);
        hist_add(s.hist, u & 0x3FFu, valid);
    }
    __syncthreads();
    if (tid < 32) select_from_top(s.hist, 1024, kk2, &s.bC, &s.kkC, &s.cntC);
    __syncthreads();

    const uint32_t u_t = (b1 << 21) | (b2 << 10) | s.bC;
    const uint32_t A = s.kkC;
    const uint32_t T = s.cntC;
    const bool keep_all_ties = (A == T);

    if (use_cand) {
        for (uint32_t q = tid; q < cc2; q += NT) {
            uint32_t u = s.u.sp.cand[q];
            bool keep = (u > u_t);
            if (!keep && u == u_t) {
                if (keep_all_ties) keep = true;
                else {
                    uint32_t rank = 0;
                    for (uint32_t p = 0; p < cc2; p++)
                        rank += (s.u.sp.cand[p] == u_t && s.u.sp.cidx[p] < s.u.sp.cidx[q]);
                    keep = (rank < A);
                }
            }
            if (keep) outf[s.u.sp.cidx[q]] = u2f(u);
        }
    } else {
        for (int i = tid; i < DCOLS; i += NT) {
            uint32_t u = f2u(rowf[i]);
            if ((u >> 21) != b1) continue;
            bool keep = (u > u_t);
            if (!keep && u == u_t) {
                if (keep_all_ties) keep = true;
                else {
                    uint32_t rank = 0;
                    for (int q = 0; q < i; q++) rank += (f2u(rowf[q]) == u_t);
                    keep = (rank < A);
                }
            }
            if (keep) outf[i] = u2f(u);
        }
    }
}

extern "C" void kernel_launch(void* const* d_in, const int* in_sizes, int n_in,
                              void* d_out, int out_size) {
    const float* in = (const float*)d_in[0];
    float* out = (float*)d_out;
    int rows = in_sizes[0] / DCOLS;   // 4096
    size_t smem_bytes = sizeof(Smem);
    cudaFuncSetAttribute(wta_kernel, cudaFuncAttributeMaxDynamicSharedMemorySize, (int)smem_bytes);
    wta_kernel<<<rows, NT, smem_bytes>>>(in, out, rows);
}

// round 17
// speedup vs baseline: 1.0151x; 1.0151x over previous
#include <cuda_runtime.h>
#include <stdint.h>
#include <math_constants.h>

// WinnerTakeAll: per-row top-k (k=1000), rows of 20000 fp32, 4096 rows.
// NT=512, 4 CTAs/SM. R15 two-threshold slot-direct kernel + peeled stream:
// iterations 0-8 are unconditional (no valid predicate), iter 0 reuses the
// sample-phase load, only iter 9 is guarded (tid<392).
//  1. t_hi = mu+1.751*sigma (~800 sure winners), t_lo = mu+1.514*sigma.
//  2. hot stream: out = v>=t_lo ? v : 0; count c_above (v>=t_hi);
//     band [t_lo,t_hi) keys+indices -> per-thread SMEM slots (~500 total).
//  3. tail (SMEM only): normalized 1-pass hist + select2 -> bin <=32 keys ->
//     warp-register exact select -> zero band losers.
//  4. guards (overflow, c_above>=k, c_above+ccount<k, bin>32, tie straddle)
//     -> exact slow path (full radix, rewrites entire row).

#define DCOLS    20000
#define KKEEP    1000u
#define NT       512
#define NWARP    16
#define NBINS    2048
#define SLOTS    12
#define CAND_CAP 1024
#define ZHI      1.751f
#define ZLO      1.514f

struct Smem {
    union {
        struct {                       // fast path: per-thread slots
            uint32_t skey[NT * SLOTS]; // 24576 B
            uint16_t sidx[NT * SLOTS]; // 12288 B
        } f;
        struct {                       // slow path: compact candidate arrays
            uint32_t cand[CAND_CAP];   // 4096 B
            uint16_t cidx[CAND_CAP];   // 2048 B
        } sp;
    } u;                               // 36864 B
    uint32_t hist[NBINS];              // 8192 B
    uint32_t segsum[256];              // 1 KB (select2 scratch + tie-collect)
    float    redsum[NWARP], redsq[NWARP];
    float    t_hi, t_lo;
    uint32_t cand_count, overflow, c_above, tcnt;
    uint32_t bA, kkA, bB, kkB, bC, kkC, cntC;
};

__device__ __forceinline__ uint32_t f2u(float f) {
    uint32_t b = __float_as_uint(f);
    return b ^ ((b & 0x80000000u) ? 0xFFFFFFFFu : 0x80000000u);
}
__device__ __forceinline__ float u2f(uint32_t u) {
    uint32_t b = (u & 0x80000000u) ? (u ^ 0x80000000u) : (u ^ 0xFFFFFFFFu);
    return __uint_as_float(b);
}

// Warp-aggregated histogram add (ALL 32 lanes participate). Slow path only.
__device__ __forceinline__ void hist_add(uint32_t* hist, uint32_t bin, bool valid) {
    uint32_t key = valid ? bin : 0xFFFFFFFFu;
    unsigned m = __match_any_sync(0xFFFFFFFFu, key);
    int leader = __ffs(m) - 1;
    if (valid && (int)(threadIdx.x & 31) == leader)
        atomicAdd(&hist[bin], (uint32_t)__popc(m));
}

// Serial top-down scan (slow path only; warp 0).
__device__ __forceinline__ void select_from_top(const uint32_t* hist, int nbins, uint32_t kk,
                                                uint32_t* out_bin, uint32_t* out_kk, uint32_t* out_cnt) {
    int lane = threadIdx.x & 31;
    uint32_t cum = 0;
    for (int base = nbins - 32; base >= 0; base -= 32) {
        uint32_t v = hist[base + 31 - lane];
        uint32_t incl = v;
        #pragma unroll
        for (int off = 1; off < 32; off <<= 1) {
            uint32_t t = __shfl_up_sync(0xFFFFFFFFu, incl, off);
            if (lane >= off) incl += t;
        }
        uint32_t total = __shfl_sync(0xFFFFFFFFu, incl, 31);
        unsigned hm = __ballot_sync(0xFFFFFFFFu, cum + incl >= kk);
        if (hm) {
            int l = __ffs(hm) - 1;
            if (lane == l) {
                *out_bin = (uint32_t)(base + 31 - l);
                *out_kk  = kk - cum - (incl - v);
                *out_cnt = v;
            }
            return;
        }
        cum += total;
    }
    if (lane == 0) { *out_bin = 0; *out_kk = 1; *out_cnt = 1; }
}

// Block-parallel select: segment sums (8 bins/seg), then warp 0 scans segments.
__device__ __forceinline__ void select2(Smem* s, const uint32_t* hist, int nbins, uint32_t kk,
                                        uint32_t* out_bin, uint32_t* out_kk, uint32_t* out_cnt,
                                        int tid) {
    int nseg = nbins >> 3;
    const uint4* h4 = reinterpret_cast<const uint4*>(hist);
    for (int i = tid; i < nseg; i += NT) {
        uint4 x = h4[2 * i], y = h4[2 * i + 1];
        s->segsum[i] = x.x + x.y + x.z + x.w + y.x + y.y + y.z + y.w;
    }
    __syncthreads();
    if (tid < 32) {
        int lane = tid;
        uint32_t cum = 0;
        bool done = false;
        for (int base = nseg - 32; base >= 0 && !done; base -= 32) {
            uint32_t v = s->segsum[base + 31 - lane];
            uint32_t incl = v;
            #pragma unroll
            for (int off = 1; off < 32; off <<= 1) {
                uint32_t t = __shfl_up_sync(0xFFFFFFFFu, incl, off);
                if (lane >= off) incl += t;
            }
            uint32_t total = __shfl_sync(0xFFFFFFFFu, incl, 31);
            unsigned hm = __ballot_sync(0xFFFFFFFFu, cum + incl >= kk);
            if (hm) {
                int l = __ffs(hm) - 1;
                if (lane == l) {
                    int seg = base + 31 - l;
                    uint32_t kk_s = kk - cum - (incl - v);
                    for (int b = seg * 8 + 7; b >= seg * 8; b--) {
                        uint32_t c = hist[b];
                        if (kk_s <= c) { *out_bin = (uint32_t)b; *out_kk = kk_s; *out_cnt = c; break; }
                        kk_s -= c;
                    }
                }
                done = true;
            }
            cum += total;
        }
        if (!done && lane == 0) { *out_bin = 0; *out_kk = 1; *out_cnt = 1; }
    }
    __syncthreads();
}

extern "C" __global__ void __launch_bounds__(NT, 4)
wta_kernel(const float* __restrict__ in, float* __restrict__ out, int rows) {
    __shared__ Smem s;

    const int row = blockIdx.x;
    if (row >= rows) return;
    const int tid = threadIdx.x;
    const int lane = tid & 31;
    const int w = tid >> 5;

    const float*  rowf = in + (size_t)row * DCOLS;
    const float4* rowp = reinterpret_cast<const float4*>(rowf);
    float4* outp = reinterpret_cast<float4*>(out + (size_t)row * DCOLS);
    float*  outf = out + (size_t)row * DCOLS;
    const int nvec = DCOLS / 4;                 // 5000
    const int niter = (nvec + NT - 1) / NT;     // 10

    if (tid == 0) { s.cand_count = 0; s.overflow = 0; s.c_above = 0; s.tcnt = 0; }
    reinterpret_cast<uint4*>(s.hist)[tid] = make_uint4(0, 0, 0, 0);   // 8KB clear

    // ---- phase 1: thresholds from sample mean/std (2048 samples) ----
    // The sample IS stream iteration 0's data; keep it in registers.
    const float4 a0 = rowp[tid];
    {
        float sum = a0.x + a0.y + a0.z + a0.w;
        float sq = fmaf(a0.x, a0.x, fmaf(a0.y, a0.y, fmaf(a0.z, a0.z, a0.w * a0.w)));
        #pragma unroll
        for (int off = 16; off > 0; off >>= 1) {
            sum += __shfl_down_sync(0xFFFFFFFFu, sum, off);
            sq  += __shfl_down_sync(0xFFFFFFFFu, sq,  off);
        }
        if (lane == 0) { s.redsum[w] = sum; s.redsq[w] = sq; }
        __syncthreads();
        if (tid == 0) {
            float ts = 0.f, tq = 0.f;
            #pragma unroll
            for (int i = 0; i < NWARP; i++) { ts += s.redsum[i]; tq += s.redsq[i]; }
            float mu = ts * (1.0f / 2048.0f);
            float var = tq * (1.0f / 2048.0f) - mu * mu;
            float sd = sqrtf(fmaxf(var, 0.0f));
            s.t_hi = fmaf(ZHI, sd, mu);
            s.t_lo = fmaf(ZLO, sd, mu);
        }
        __syncthreads();
    }
    const float t_hi = s.t_hi;
    const float t_lo = s.t_lo;

    // ---- phase 2: hot stream, peeled (iters 0-8 full, iter 9 guarded) ----
    uint32_t nloc = 0;
    uint32_t my_above = 0;
    const uint32_t slotbase = (uint32_t)tid * SLOTS;

    #pragma unroll
    for (int it = 0; it < 9; it++) {
        int i = tid + it * NT;
        float4 v = (it == 0) ? a0 : rowp[i];
        float vv[4] = { v.x, v.y, v.z, v.w };
        float ov[4];
        #pragma unroll
        for (int j = 0; j < 4; j++) {
            bool ab = vv[j] >= t_hi;           // sure winner
            bool ge = vv[j] >= t_lo;           // winner or band
            ov[j] = ge ? vv[j] : 0.0f;
            my_above += ab;
            if (ge && !ab) {                   // band candidate: store key + index
                if (nloc < SLOTS) {
                    s.u.f.skey[slotbase + nloc] = f2u(vv[j]);
                    s.u.f.sidx[slotbase + nloc] = (uint16_t)(i * 4 + j);
                }
                nloc++;
            }
        }
        float4 o; o.x = ov[0]; o.y = ov[1]; o.z = ov[2]; o.w = ov[3];
        outp[i] = o;
    }
    // iteration 9: only tid < 392 valid (4608 + tid < 5000)
    if (tid < nvec - 9 * NT) {
        int i = tid + 9 * NT;
        float4 v = rowp[i];
        float vv[4] = { v.x, v.y, v.z, v.w };
        float ov[4];
        #pragma unroll
        for (int j = 0; j < 4; j++) {
            bool ab = vv[j] >= t_hi;
            bool ge = vv[j] >= t_lo;
            ov[j] = ge ? vv[j] : 0.0f;
            my_above += ab;
            if (ge && !ab) {
                if (nloc < SLOTS) {
                    s.u.f.skey[slotbase + nloc] = f2u(vv[j]);
                    s.u.f.sidx[slotbase + nloc] = (uint16_t)(i * 4 + j);
                }
                nloc++;
            }
        }
        float4 o; o.x = ov[0]; o.y = ov[1]; o.z = ov[2]; o.w = ov[3];
        outp[i] = o;
    }
    uint32_t nstore = nloc < SLOTS ? nloc : SLOTS;
    if (nloc > SLOTS) s.overflow = 1;

    // ---- reduce c_above and ccount (one warp-reduce each, one atomic/warp) ----
    uint32_t my_band = nstore;
    #pragma unroll
    for (int off = 16; off > 0; off >>= 1) {
        my_above += __shfl_down_sync(0xFFFFFFFFu, my_above, off);
        my_band  += __shfl_down_sync(0xFFFFFFFFu, my_band,  off);
    }
    if (lane == 0) {
        if (my_above) atomicAdd(&s.c_above, my_above);
        if (my_band)  atomicAdd(&s.cand_count, my_band);
    }
    __syncthreads();

    const uint32_t ccount = s.cand_count;
    const uint32_t c_above = s.c_above;
    bool need_slow = !((!s.overflow) && (c_above < KKEEP) && (c_above + ccount >= KKEEP));

    if (!need_slow) {
        // ===== FAST TAIL: slot-direct, SMEM only =====
        const uint32_t kk = KKEEP - c_above;
        const uint32_t u_lo = f2u(t_lo);
        uint32_t R = f2u(t_hi) - u_lo;
        if (R == 0) R = 1;
        const int shift = __clz(R);

        // 1-pass normalized histogram from slots (plain atomics; bins ~unique)
        for (uint32_t n = 0; n < nstore; n++) {
            uint32_t u = s.u.f.skey[slotbase + n];
            uint32_t nb = ((u - u_lo) << shift) >> 21;
            atomicAdd(&s.hist[nb], 1u);
        }
        __syncthreads();
        select2(&s, s.hist, NBINS, kk, &s.bA, &s.kkA, &s.cntC, tid);
        const uint32_t nbin = s.bA;
        const uint32_t kk1 = s.kkA;
        const uint32_t cnt1 = s.cntC;

        if (cnt1 > 32) {
            need_slow = true;                   // pathological tie mass in one bin
        } else {
            // collect the <=32 keys of the target bin
            for (uint32_t n = 0; n < nstore; n++) {
                uint32_t u = s.u.f.skey[slotbase + n];
                uint32_t nb = ((u - u_lo) << shift) >> 21;
                if (nb == nbin) {
                    uint32_t pos = atomicAdd(&s.tcnt, 1u);
                    s.segsum[pos] = u;          // pos < 32 (cnt1 <= 32)
                }
            }
            __syncthreads();
            // warp-register exact selection among <=32 keys
            if (tid < 32) {
                uint32_t myu = (tid < (int)cnt1) ? s.segsum[tid] : 0;
                uint32_t gt = 0, eq = 0;
                for (uint32_t p = 0; p < cnt1; p++) {
                    uint32_t up = __shfl_sync(0xFFFFFFFFu, myu, p);
                    gt += (up > myu);
                    eq += (up == myu);
                }
                bool sel = (tid < (int)cnt1) && (gt < kk1) && (kk1 <= gt + eq);
                unsigned m = __ballot_sync(0xFFFFFFFFu, sel);
                int l = __ffs(m) - 1;
                if (tid == l) { s.bB = myu; s.kkB = kk1 - gt; s.bC = eq; }
            }
            __syncthreads();
            const uint32_t u_t = s.bB;
            const uint32_t A = s.kkB;
            const uint32_t T = s.bC;
            if (A != T) {
                need_slow = true;               // ties straddle boundary (rare)
            } else {
                // zero losers straight from slots
                for (uint32_t n = 0; n < nstore; n++) {
                    uint32_t u = s.u.f.skey[slotbase + n];
                    if (u < u_t) outf[s.u.f.sidx[slotbase + n]] = 0.0f;
                }
                return;
            }
        }
    }

    // ================= SLOW PATH (rare; rewrites entire row) =================
    __syncthreads();
    reinterpret_cast<uint4*>(s.hist)[tid] = make_uint4(0, 0, 0, 0);
    if (tid == 0) s.cand_count = 0;
    __syncthreads();

    #pragma unroll 1
    for (int it = 0; it < niter; it++) {
        int i = tid + it * NT;
        bool valid = i < nvec;
        uint32_t u0 = 0, u1 = 0, u2 = 0, u3 = 0;
        if (valid) {
            float4 v = rowp[i];
            u0 = f2u(v.x); u1 = f2u(v.y); u2 = f2u(v.z); u3 = f2u(v.w);
        }
        hist_add(s.hist, u0 >> 21, valid);
        hist_add(s.hist, u1 >> 21, valid);
        hist_add(s.hist, u2 >> 21, valid);
        hist_add(s.hist, u3 >> 21, valid);
    }
    __syncthreads();
    if (tid < 32) select_from_top(s.hist, NBINS, KKEEP, &s.bA, &s.kkA, &s.cntC);
    __syncthreads();
    const uint32_t b1 = s.bA;
    const uint32_t kk1s = s.kkA;

    #pragma unroll 1
    for (int it = 0; it < niter; it++) {
        int i = tid + it * NT;
        if (i >= nvec) break;
        float4 v = rowp[i];
        float vv[4] = { v.x, v.y, v.z, v.w };
        uint32_t uu[4] = { f2u(v.x), f2u(v.y), f2u(v.z), f2u(v.w) };
        float ov[4];
        #pragma unroll
        for (int j = 0; j < 4; j++) {
            uint32_t bin = uu[j] >> 21;
            ov[j] = (bin > b1) ? vv[j] : 0.0f;
            if (bin == b1) {
                uint32_t pos = atomicAdd(&s.cand_count, 1u);
                if (pos < CAND_CAP) { s.u.sp.cand[pos] = uu[j]; s.u.sp.cidx[pos] = (uint16_t)(i * 4 + j); }
            }
        }
        float4 o; o.x = ov[0]; o.y = ov[1]; o.z = ov[2]; o.w = ov[3];
        outp[i] = o;
    }
    __syncthreads();

    const uint32_t cc2 = s.cand_count;
    const bool use_cand = (cc2 <= CAND_CAP);
    const int nitems = use_cand ? (int)cc2 : DCOLS;
    const int niterB = (nitems + NT - 1) / NT;

    reinterpret_cast<uint4*>(s.hist)[tid] = make_uint4(0, 0, 0, 0);
    __syncthreads();
    #pragma unroll 1
    for (int it = 0; it < niterB; it++) {
        int i = tid + it * NT;
        bool valid = i < nitems;
        uint32_t u = 0;
        if (valid) u = use_cand ? s.u.sp.cand[i] : f2u(rowf[i]);
        valid = valid && (use_cand || ((u >> 21) == b1));
        hist_add(s.hist, (u >> 10) & 0x7FFu, valid);
    }
    __syncthreads();
    if (tid < 32) select_from_top(s.hist, NBINS, kk1s, &s.bB, &s.kkB, &s.cntC);
    __syncthreads();
    const uint32_t b2 = s.bB;
    const uint32_t kk2 = s.kkB;
    const uint32_t pref22 = (b1 << 11) | b2;

    for (int i = tid; i < 1024; i += NT) s.hist[i] = 0;
    __syncthreads();
    #pragma unroll 1
    for (int it = 0; it < niterB; it++) {
        int i = tid + it * NT;
        bool valid = i < nitems;
        uint32_t u = 0;
        if (valid) u = use_cand ? s.u.sp.cand[i] : f2u(rowf[i]);
        valid = valid && ((u >> 10) == pref22);
        hist_add(s.hist, u & 0x3FFu, valid);
    }
    __syncthreads();
    if (tid < 32) select_from_top(s.hist, 1024, kk2, &s.bC, &s.kkC, &s.cntC);
    __syncthreads();

    const uint32_t u_t = (b1 << 21) | (b2 << 10) | s.bC;
    const uint32_t A = s.kkC;
    const uint32_t T = s.cntC;
    const bool keep_all_ties = (A == T);

    if (use_cand) {
        for (uint32_t q = tid; q < cc2; q += NT) {
            uint32_t u = s.u.sp.cand[q];
            bool keep = (u > u_t);
            if (!keep && u == u_t) {
                if (keep_all_ties) keep = true;
                else {
                    uint32_t rank = 0;
                    for (uint32_t p = 0; p < cc2; p++)
                        rank += (s.u.sp.cand[p] == u_t && s.u.sp.cidx[p] < s.u.sp.cidx[q]);
                    keep = (rank < A);
                }
            }
            if (keep) outf[s.u.sp.cidx[q]] = u2f(u);
        }
    } else {
        for (int i = tid; i < DCOLS; i += NT) {
            uint32_t u = f2u(rowf[i]);
            if ((u >> 21) != b1) continue;
            bool keep = (u > u_t);
            if (!keep && u == u_t) {
                if (keep_all_ties) keep = true;
                else {
                    uint32_t rank = 0;
                    for (int q = 0; q < i; q++) rank += (f2u(rowf[q]) == u_t);
                    keep = (rank < A);
                }
            }
            if (keep) outf[i] = u2f(u);
        }
    }
}

extern "C" void kernel_launch(void* const* d_in, const int* in_sizes, int n_in,
                              void* d_out, int out_size) {
    const float* in = (const float*)d_in[0];
    float* out = (float*)d_out;
    int rows = in_sizes[0] / DCOLS;   // 4096
    wta_kernel<<<rows, NT>>>(in, out, rows);
}